// round 1
// baseline (speedup 1.0000x reference)
#include <cuda_runtime.h>
#include <math.h>

#define BATCH 8
#define SEQ   1024
#define HID   1024
#define NHEAD 16
#define HDIM  64
#define N3    3072
#define MROWS 8192
#define KDIM  1024

// Scratch: Q, K, V each [B, NH, S, HD] = 8*16*1024*64 floats (32 MB)
__device__ float g_Q[BATCH*NHEAD*SEQ*HDIM];
__device__ float g_K[BATCH*NHEAD*SEQ*HDIM];
__device__ float g_V[BATCH*NHEAD*SEQ*HDIM];

typedef unsigned long long u64;

__device__ __forceinline__ void fma2(u64& d, u64 a, u64 b) {
    asm("fma.rn.f32x2 %0, %1, %2, %3;" : "=l"(d) : "l"(a), "l"(b), "l"(d));
}
__device__ __forceinline__ void mul2(u64& d, u64 a) {
    asm("mul.rn.f32x2 %0, %1, %2;" : "=l"(d) : "l"(d), "l"(a));
}
__device__ __forceinline__ u64 pack2(float x, float y) {
    u64 r; asm("mov.b64 %0, {%1,%2};" : "=l"(r) : "f"(x), "f"(y)); return r;
}
__device__ __forceinline__ float2 unpack2(u64 v) {
    float2 r; asm("mov.b64 {%0,%1}, %2;" : "=f"(r.x), "=f"(r.y) : "l"(v)); return r;
}

// ============================================================================
// Kernel 1: QKV GEMM  [8192,1024] x [1024,3072] + bias, scattered into Q/K/V
// 128x128 tile, BK=16, 256 threads, 8x8 per thread, f32x2 packed over N.
// ============================================================================
#define BM 128
#define BN 128
#define BK 16

__global__ void __launch_bounds__(256, 2) qkv_gemm(
    const float* __restrict__ A, const float* __restrict__ Wq,
    const float* __restrict__ bias)
{
    __shared__ float As[BK][BM];   // transposed A tile
    __shared__ float Bs[BK][BN];
    const int tid = threadIdx.x;
    const int tx = tid & 15, ty = tid >> 4;
    const int bn = blockIdx.x, bm = blockIdx.y;
    const float* Ab = A + (size_t)bm * BM * KDIM;
    const float* Bb = Wq + bn * BN;

    u64 acc[8][4];
    #pragma unroll
    for (int i = 0; i < 8; i++)
        #pragma unroll
        for (int j = 0; j < 4; j++) acc[i][j] = 0ull;

    const int arow = tid >> 2;           // 0..63
    const int ac   = (tid & 3) << 2;     // 0,4,8,12
    const int brow = tid >> 5;           // 0..7
    const int bc   = (tid & 31) << 2;    // 0..124

    for (int k0 = 0; k0 < KDIM; k0 += BK) {
        #pragma unroll
        for (int r = 0; r < 2; r++) {
            int row = arow + r * 64;
            float4 v = *(const float4*)(Ab + (size_t)row * KDIM + k0 + ac);
            As[ac+0][row] = v.x; As[ac+1][row] = v.y;
            As[ac+2][row] = v.z; As[ac+3][row] = v.w;
        }
        #pragma unroll
        for (int r = 0; r < 2; r++) {
            int row = brow + r * 8;
            *(float4*)(&Bs[row][bc]) = *(const float4*)(Bb + (size_t)(k0 + row) * N3 + bc);
        }
        __syncthreads();
        #pragma unroll
        for (int k = 0; k < BK; k++) {
            float a[8];
            *(float4*)(a)     = *(const float4*)(&As[k][ty*8]);
            *(float4*)(a + 4) = *(const float4*)(&As[k][ty*8 + 4]);
            u64 b2[4];
            {
                ulonglong2 t0 = *(const ulonglong2*)(&Bs[k][tx*8]);
                ulonglong2 t1 = *(const ulonglong2*)(&Bs[k][tx*8 + 4]);
                b2[0] = t0.x; b2[1] = t0.y; b2[2] = t1.x; b2[3] = t1.y;
            }
            #pragma unroll
            for (int i = 0; i < 8; i++) {
                u64 aa = pack2(a[i], a[i]);
                #pragma unroll
                for (int j = 0; j < 4; j++) fma2(acc[i][j], aa, b2[j]);
            }
        }
        __syncthreads();
    }

    // Epilogue: add bias, scatter into g_Q/g_K/g_V with [B,NH,S,HD] layout.
    // column c -> head n = c/192, tensor t = (c%192)/64, d = c%64
    const int m0 = bm * BM + ty * 8;
    const int c0 = bn * BN + tx * 8;
    #pragma unroll
    for (int i = 0; i < 8; i++) {
        const int mm = m0 + i;
        const int bb = mm >> 10;       // / SEQ
        const int ss = mm & 1023;
        #pragma unroll
        for (int j2 = 0; j2 < 4; j2++) {
            float2 v = unpack2(acc[i][j2]);
            #pragma unroll
            for (int u = 0; u < 2; u++) {
                int c = c0 + j2 * 2 + u;
                float val = (u ? v.y : v.x) + bias[c];
                int n  = c / 192;
                int rr = c - n * 192;
                int t  = rr >> 6;
                int d  = rr & 63;
                float* dst = (t == 0) ? g_Q : (t == 1) ? g_K : g_V;
                dst[(((size_t)(bb * NHEAD + n) * SEQ + ss) << 6) + d] = val;
            }
        }
    }
}

// ============================================================================
// Kernel 2: fused attention, flash-style online softmax, fp32.
// One CTA per (b, h, 64-row q-tile). 256 threads; thread owns a 4x4 score
// subtile and a 4x4 O subtile (same rows). f32x2 packed over d.
// X tile is XOR-swizzled (float4 unit u -> u ^ (row>>2)) and reused: K then P.
// ============================================================================
__global__ void __launch_bounds__(256, 2) attn_kernel(
    const int* __restrict__ mask, float* __restrict__ out)
{
    __shared__ float4 Qs4[64 * 16];
    __shared__ float4 Xs4[64 * 16];   // K tile (swizzled), then P tile (swizzled)
    __shared__ float4 Vs4[64 * 16];

    const int tid = threadIdx.x;
    const int tx = tid & 15, ty = tid >> 4;
    const int qt = blockIdx.x & 15;
    const int bh = blockIdx.x >> 4;
    const int bb = bh >> 4;
    const int hh = bh & 15;
    const size_t base = (size_t)bh * (SEQ * HDIM);
    const int i0 = ty * 4, j0 = tx * 4;

    // Load Q tile (contiguous 64x64)
    const float4* Qg = (const float4*)(g_Q + base + (size_t)qt * 64 * HDIM);
    #pragma unroll
    for (int r = 0; r < 4; r++) Qs4[tid + r * 256] = Qg[tid + r * 256];

    const int* mrow = mask + bb * SEQ;

    float mrun[4], lrun[4];
    u64 o2[4][2];
    #pragma unroll
    for (int i = 0; i < 4; i++) {
        mrun[i] = -1e30f; lrun[i] = 0.0f;
        o2[i][0] = 0ull; o2[i][1] = 0ull;
    }

    for (int kt = 0; kt < 16; kt++) {
        __syncthreads();   // protect X/V overwrite vs previous tile's reads
        const float4* Kg = (const float4*)(g_K + base + (size_t)kt * 64 * HDIM);
        const float4* Vg = (const float4*)(g_V + base + (size_t)kt * 64 * HDIM);
        #pragma unroll
        for (int r = 0; r < 4; r++) {
            int idx = tid + r * 256;
            int row = idx >> 4, u = idx & 15;
            Xs4[row * 16 + (u ^ (row >> 2))] = Kg[idx];
            Vs4[idx] = Vg[idx];
        }
        __syncthreads();

        // --- QK^T: acc2 packed over d-parity (horizontal add at end) ---
        u64 acc2[4][4];
        #pragma unroll
        for (int i = 0; i < 4; i++)
            #pragma unroll
            for (int j = 0; j < 4; j++) acc2[i][j] = 0ull;

        #pragma unroll
        for (int d4 = 0; d4 < 16; d4++) {
            ulonglong2 qv[4], kv[4];
            #pragma unroll
            for (int i = 0; i < 4; i++)
                qv[i] = *(const ulonglong2*)&Qs4[(i0 + i) * 16 + d4];
            #pragma unroll
            for (int j = 0; j < 4; j++)
                kv[j] = *(const ulonglong2*)&Xs4[(j0 + j) * 16 + (d4 ^ tx)];
            #pragma unroll
            for (int i = 0; i < 4; i++)
                #pragma unroll
                for (int j = 0; j < 4; j++) {
                    fma2(acc2[i][j], qv[i].x, kv[j].x);
                    fma2(acc2[i][j], qv[i].y, kv[j].y);
                }
        }

        // --- scores: *sqrt(64), mask -> -10000 (matches reference exactly) ---
        float sc[4][4];
        #pragma unroll
        for (int i = 0; i < 4; i++)
            #pragma unroll
            for (int j = 0; j < 4; j++) {
                float2 v = unpack2(acc2[i][j]);
                sc[i][j] = (v.x + v.y) * 8.0f;
            }
        const int kbase = kt * 64;
        #pragma unroll
        for (int j = 0; j < 4; j++) {
            if (mrow[kbase + j0 + j] != 0) {
                sc[0][j] = -10000.0f; sc[1][j] = -10000.0f;
                sc[2][j] = -10000.0f; sc[3][j] = -10000.0f;
            }
        }

        // --- online softmax update (rows shared across the 16 tx lanes) ---
        float p[4][4];
        #pragma unroll
        for (int i = 0; i < 4; i++) {
            float tm = fmaxf(fmaxf(sc[i][0], sc[i][1]), fmaxf(sc[i][2], sc[i][3]));
            #pragma unroll
            for (int w = 1; w < 16; w <<= 1)
                tm = fmaxf(tm, __shfl_xor_sync(0xffffffffu, tm, w));
            float mnew = fmaxf(mrun[i], tm);
            float ts = 0.0f;
            #pragma unroll
            for (int j = 0; j < 4; j++) {
                p[i][j] = expf(sc[i][j] - mnew);
                ts += p[i][j];
            }
            #pragma unroll
            for (int w = 1; w < 16; w <<= 1)
                ts += __shfl_xor_sync(0xffffffffu, ts, w);
            float alpha = expf(mrun[i] - mnew);
            lrun[i] = lrun[i] * alpha + ts;
            mrun[i] = mnew;
            u64 aa = pack2(alpha, alpha);
            mul2(o2[i][0], aa);
            mul2(o2[i][1], aa);
        }
        __syncthreads();   // all K reads of X done

        // write P tile into X (swizzled)
        #pragma unroll
        for (int i = 0; i < 4; i++) {
            float4 pv = make_float4(p[i][0], p[i][1], p[i][2], p[i][3]);
            Xs4[(i0 + i) * 16 + (tx ^ ((i0 + i) >> 2))] = pv;
        }
        __syncthreads();

        // --- O += P @ V : packed over d (thread's d-cols = tx*4..tx*4+3) ---
        #pragma unroll
        for (int j4 = 0; j4 < 16; j4++) {
            float4 pr[4];
            ulonglong2 vv[4];
            #pragma unroll
            for (int i = 0; i < 4; i++)
                pr[i] = Xs4[(i0 + i) * 16 + (j4 ^ ((i0 + i) >> 2))];
            #pragma unroll
            for (int jj = 0; jj < 4; jj++)
                vv[jj] = *(const ulonglong2*)&Vs4[(j4 * 4 + jj) * 16 + tx];
            #pragma unroll
            for (int i = 0; i < 4; i++) {
                const float* pp = (const float*)&pr[i];
                #pragma unroll
                for (int jj = 0; jj < 4; jj++) {
                    u64 ppp = pack2(pp[jj], pp[jj]);
                    fma2(o2[i][0], ppp, vv[jj].x);
                    fma2(o2[i][1], ppp, vv[jj].y);
                }
            }
        }
    }

    // --- epilogue: normalize and write out[b, s, h*64 + d] ---
    #pragma unroll
    for (int i = 0; i < 4; i++) {
        float inv = 1.0f / lrun[i];
        float2 a = unpack2(o2[i][0]);
        float2 b = unpack2(o2[i][1]);
        float4 res = make_float4(a.x * inv, a.y * inv, b.x * inv, b.y * inv);
        int q = qt * 64 + i0 + i;
        float* dst = out + ((size_t)(bb * SEQ + q)) * HID + hh * 64 + tx * 4;
        *(float4*)dst = res;
    }
}

extern "C" void kernel_launch(void* const* d_in, const int* in_sizes, int n_in,
                              void* d_out, int out_size)
{
    const float* hidden = (const float*)d_in[0];
    const int*   mask   = (const int*)  d_in[1];
    const float* w_qkv  = (const float*)d_in[2];
    const float* b_qkv  = (const float*)d_in[3];
    float* out = (float*)d_out;

    dim3 g1(N3 / BN, MROWS / BM);
    qkv_gemm<<<g1, 256>>>(hidden, w_qkv, b_qkv);
    attn_kernel<<<BATCH * NHEAD * (SEQ / 64), 256>>>(mask, out);
}

// round 7
// speedup vs baseline: 1.5493x; 1.5493x over previous
#include <cuda_runtime.h>
#include <cuda_bf16.h>
#include <cstdint>
#include <math.h>

#define BATCH 8
#define SEQ   1024
#define HID   1024
#define NHEAD 16
#define HDIM  64
#define N3    3072
#define MROWS 8192
#define KDIM  1024

typedef unsigned long long u64;
typedef unsigned int u32;

// ---------------------------------------------------------------------------
// Scratch globals
// ---------------------------------------------------------------------------
__device__ __align__(16) float g_Q[BATCH*NHEAD*SEQ*HDIM];
__device__ __align__(16) float g_K[BATCH*NHEAD*SEQ*HDIM];
__device__ __align__(16) float g_V[BATCH*NHEAD*SEQ*HDIM];

// 2-way bf16 splits (hi, mid) of hidden (A) and W^T (B)
__device__ __align__(16) __nv_bfloat16 g_Ah[MROWS*KDIM];
__device__ __align__(16) __nv_bfloat16 g_Am[MROWS*KDIM];
__device__ __align__(16) __nv_bfloat16 g_Wh[N3*KDIM];
__device__ __align__(16) __nv_bfloat16 g_Wm[N3*KDIM];

// ---------------------------------------------------------------------------
// helpers
// ---------------------------------------------------------------------------
__device__ __forceinline__ void fma2(u64& d, u64 a, u64 b) {
    asm("fma.rn.f32x2 %0, %1, %2, %3;" : "=l"(d) : "l"(a), "l"(b), "l"(d));
}
__device__ __forceinline__ void mul2(u64& d, u64 a) {
    asm("mul.rn.f32x2 %0, %1, %2;" : "=l"(d) : "l"(d), "l"(a));
}
__device__ __forceinline__ u64 pack2(float x, float y) {
    u64 r; asm("mov.b64 %0, {%1,%2};" : "=l"(r) : "f"(x), "f"(y)); return r;
}
__device__ __forceinline__ float2 unpack2(u64 v) {
    float2 r; asm("mov.b64 {%0,%1}, %2;" : "=f"(r.x), "=f"(r.y) : "l"(v)); return r;
}
__device__ __forceinline__ u32 su32(const void* p) {
    u32 a;
    asm("{ .reg .u64 t; cvta.to.shared.u64 t, %1; cvt.u32.u64 %0, t; }" : "=r"(a) : "l"(p));
    return a;
}
__device__ __forceinline__ void cp16(u32 sm, const void* g) {
    asm volatile("cp.async.cg.shared.global [%0], [%1], 16;" :: "r"(sm), "l"(g));
}
__device__ __forceinline__ void cp_commit() {
    asm volatile("cp.async.commit_group;" ::: "memory");
}
__device__ __forceinline__ void cp_wait1() {
    asm volatile("cp.async.wait_group 1;" ::: "memory");
}
__device__ __forceinline__ void cp_wait0() {
    asm volatile("cp.async.wait_group 0;" ::: "memory");
}
__device__ __forceinline__ void ldsm4(u32* r, u32 addr) {
    asm volatile("ldmatrix.sync.aligned.m8n8.x4.shared.b16 {%0,%1,%2,%3}, [%4];"
                 : "=r"(r[0]), "=r"(r[1]), "=r"(r[2]), "=r"(r[3]) : "r"(addr));
}
__device__ __forceinline__ void mma16816(float* d, const u32* a, u32 b0, u32 b1) {
    asm volatile(
        "mma.sync.aligned.m16n8k16.row.col.f32.bf16.bf16.f32 "
        "{%0,%1,%2,%3}, {%4,%5,%6,%7}, {%8,%9}, {%0,%1,%2,%3};"
        : "+f"(d[0]), "+f"(d[1]), "+f"(d[2]), "+f"(d[3])
        : "r"(a[0]), "r"(a[1]), "r"(a[2]), "r"(a[3]), "r"(b0), "r"(b1));
}

// ---------------------------------------------------------------------------
// split kernels: fp32 -> bf16 hi/mid
// ---------------------------------------------------------------------------
struct __align__(8) BF4 { __nv_bfloat16 a, b, c, d; };

__device__ __forceinline__ void split2(float x, __nv_bfloat16& h, __nv_bfloat16& m) {
    h = __float2bfloat16(x);
    m = __float2bfloat16(x - __bfloat162float(h));
}

__global__ void __launch_bounds__(256) split_hidden(const float* __restrict__ x) {
    size_t i = (size_t)blockIdx.x * 256 + threadIdx.x;
    float4 v = ((const float4*)x)[i];
    BF4 H, M;
    split2(v.x, H.a, M.a);
    split2(v.y, H.b, M.b);
    split2(v.z, H.c, M.c);
    split2(v.w, H.d, M.d);
    ((BF4*)g_Ah)[i] = H;
    ((BF4*)g_Am)[i] = M;
}

// W [1024,3072] -> W^T splits [3072,1024]
__global__ void __launch_bounds__(256) split_w(const float* __restrict__ w) {
    __shared__ float tile[64][65];
    const int n0 = blockIdx.x * 64, k0 = blockIdx.y * 64;
    const int tid = threadIdx.x;
    #pragma unroll
    for (int i = 0; i < 4; i++) {
        int idx = tid + i * 256;
        int r = idx >> 4, c4 = idx & 15;
        float4 v = *(const float4*)&w[(size_t)(k0 + r) * N3 + n0 + c4 * 4];
        tile[r][c4*4+0] = v.x; tile[r][c4*4+1] = v.y;
        tile[r][c4*4+2] = v.z; tile[r][c4*4+3] = v.w;
    }
    __syncthreads();
    #pragma unroll
    for (int i = 0; i < 4; i++) {
        int idx = tid + i * 256;
        int nl = idx >> 4, k4 = idx & 15;
        BF4 H, M;
        split2(tile[k4*4+0][nl], H.a, M.a);
        split2(tile[k4*4+1][nl], H.b, M.b);
        split2(tile[k4*4+2][nl], H.c, M.c);
        split2(tile[k4*4+3][nl], H.d, M.d);
        size_t o = ((size_t)(n0 + nl) * KDIM + k0 + k4 * 4) >> 2;
        ((BF4*)g_Wh)[o] = H;
        ((BF4*)g_Wm)[o] = M;
    }
}

// ---------------------------------------------------------------------------
// QKV GEMM via mma.sync bf16 (2-split, 3 products).
// CTA: 128x128 tile, 8 warps in 2(m) x 4(n); warp = 64x32.
// K-chunk 64, double-buffered cp.async. SMEM per buf:
//   Ah[128][64] (16K) | Am (16K) | Bh (16K) | Bm (16K) = 64K
// Rows are 128B (8x16B units), XOR-swizzled unit^(row&7) for conflict-free
// cp.async stores + ldmatrix reads.
// ---------------------------------------------------------------------------
#define SMEM_BUF   65536
#define SMEM_TOTAL (2*SMEM_BUF)
#define NCHUNK     16

__device__ __forceinline__ void load_chunk(u32 base, int tid, int k0, int am0, int bn0) {
    #pragma unroll
    for (int j = 0; j < 4; j++) {
        int unit = tid + j * 256;          // 0..1023 per region
        int row = unit >> 3, u = unit & 7;
        u32 soff = row * 128 + ((u ^ (row & 7)) << 4);
        size_t ga = (size_t)(am0 + row) * KDIM + k0 + u * 8;
        cp16(base + soff,         g_Ah + ga);
        cp16(base + 16384 + soff, g_Am + ga);
        size_t gb = (size_t)(bn0 + row) * KDIM + k0 + u * 8;
        cp16(base + 32768 + soff, g_Wh + gb);
        cp16(base + 49152 + soff, g_Wm + gb);
    }
}

__global__ void __launch_bounds__(256, 1) qkv_mma(const float* __restrict__ bias) {
    extern __shared__ char smem[];
    const u32 sb = su32(smem);
    const int tid = threadIdx.x;
    const int wid = tid >> 5, lane = tid & 31;
    const int bn = blockIdx.x, bm = blockIdx.y;
    const int am0 = bm * 128, bn0 = bn * 128;
    const int wm = wid >> 2;               // 0..1  (64 rows)
    const int wn = wid & 3;                // 0..3  (32 cols)

    float acc[4][4][4];
    #pragma unroll
    for (int i = 0; i < 4; i++)
        #pragma unroll
        for (int j = 0; j < 4; j++)
            #pragma unroll
            for (int c = 0; c < 4; c++) acc[i][j][c] = 0.0f;

    // per-thread ldmatrix row pattern
    const int lrow = (lane & 7) + 8 * ((lane >> 3) & 1);   // 0..15
    const int lu   = lane >> 4;                            // 0/1 (k-half unit)

    load_chunk(sb, tid, 0, am0, bn0);
    cp_commit();

    for (int t = 0; t < NCHUNK; t++) {
        if (t + 1 < NCHUNK) {
            load_chunk(sb + ((t + 1) & 1) * SMEM_BUF, tid, (t + 1) * 64, am0, bn0);
            cp_commit();
            cp_wait1();
        } else {
            cp_wait0();
        }
        __syncthreads();

        const u32 Ah = sb + (t & 1) * SMEM_BUF;
        const u32 Am = Ah + 16384;
        const u32 Bh = Ah + 32768;
        const u32 Bm = Ah + 49152;

        #pragma unroll
        for (int kk = 0; kk < 4; kk++) {
            const int uu = 2 * kk + lu;
            u32 ah[4][4], am[4][4], bh[2][4], bmf[2][4];
            #pragma unroll
            for (int mt = 0; mt < 4; mt++) {
                int row = wm * 64 + mt * 16 + lrow;
                u32 off = row * 128 + ((uu ^ (row & 7)) << 4);
                ldsm4(ah[mt], Ah + off);
                ldsm4(am[mt], Am + off);
            }
            #pragma unroll
            for (int ng = 0; ng < 2; ng++) {
                int row = wn * 32 + ng * 16 + lrow;
                u32 off = row * 128 + ((uu ^ (row & 7)) << 4);
                ldsm4(bh[ng], Bh + off);
                ldsm4(bmf[ng], Bm + off);
            }
            #pragma unroll
            for (int mt = 0; mt < 4; mt++) {
                #pragma unroll
                for (int nt = 0; nt < 4; nt++) {
                    const int ng = nt >> 1, sel = nt & 1;
                    mma16816(acc[mt][nt], ah[mt], bh[ng][sel],  bh[ng][sel + 2]);
                    mma16816(acc[mt][nt], ah[mt], bmf[ng][sel], bmf[ng][sel + 2]);
                    mma16816(acc[mt][nt], am[mt], bh[ng][sel],  bh[ng][sel + 2]);
                }
            }
        }
        __syncthreads();
    }

    // --- epilogue: bias + scatter to g_Q/g_K/g_V ---
    // thread owns (m = mt*16 + lane/4 (+8), n = nt*8 + 2*(lane%4) (+1))
    const int bb = bm >> 3, ss0 = (bm & 7) * 128;
    const int qr = lane >> 2, qc = (lane & 3) * 2;
    #pragma unroll
    for (int nt = 0; nt < 4; nt++) {
        const int coloc = wn * 32 + nt * 8 + qc;           // 0..127
        const int hf = coloc >> 6;
        const int cb = bn * 2 + hf;
        const int head = cb / 3;
        const int tt = cb - head * 3;
        float* dst = (tt == 0) ? g_Q : (tt == 1) ? g_K : g_V;
        const int c64 = coloc & 63;
        const float2 bv = *(const float2*)&bias[bn * 128 + coloc];
        #pragma unroll
        for (int mt = 0; mt < 4; mt++) {
            #pragma unroll
            for (int half = 0; half < 2; half++) {
                const int mloc = wm * 64 + mt * 16 + qr + half * 8;
                float2 v;
                v.x = acc[mt][nt][half * 2 + 0] + bv.x;
                v.y = acc[mt][nt][half * 2 + 1] + bv.y;
                *(float2*)&dst[((size_t)(bb * NHEAD + head) * 1024 + ss0 + mloc) * 64 + c64] = v;
            }
        }
    }
}

// ============================================================================
// fused attention (unchanged): flash-style online softmax, fp32 f32x2
// ============================================================================
__global__ void __launch_bounds__(256, 2) attn_kernel(
    const int* __restrict__ mask, float* __restrict__ out)
{
    __shared__ float4 Qs4[64 * 16];
    __shared__ float4 Xs4[64 * 16];
    __shared__ float4 Vs4[64 * 16];

    const int tid = threadIdx.x;
    const int tx = tid & 15, ty = tid >> 4;
    const int qt = blockIdx.x & 15;
    const int bh = blockIdx.x >> 4;
    const int bb = bh >> 4;
    const int hh = bh & 15;
    const size_t base = (size_t)bh * (SEQ * HDIM);
    const int i0 = ty * 4, j0 = tx * 4;

    const float4* Qg = (const float4*)(g_Q + base + (size_t)qt * 64 * HDIM);
    #pragma unroll
    for (int r = 0; r < 4; r++) Qs4[tid + r * 256] = Qg[tid + r * 256];

    const int* mrow = mask + bb * SEQ;

    float mrun[4], lrun[4];
    u64 o2[4][2];
    #pragma unroll
    for (int i = 0; i < 4; i++) {
        mrun[i] = -1e30f; lrun[i] = 0.0f;
        o2[i][0] = 0ull; o2[i][1] = 0ull;
    }

    for (int kt = 0; kt < 16; kt++) {
        __syncthreads();
        const float4* Kg = (const float4*)(g_K + base + (size_t)kt * 64 * HDIM);
        const float4* Vg = (const float4*)(g_V + base + (size_t)kt * 64 * HDIM);
        #pragma unroll
        for (int r = 0; r < 4; r++) {
            int idx = tid + r * 256;
            int row = idx >> 4, u = idx & 15;
            Xs4[row * 16 + (u ^ (row >> 2))] = Kg[idx];
            Vs4[idx] = Vg[idx];
        }
        __syncthreads();

        u64 acc2[4][4];
        #pragma unroll
        for (int i = 0; i < 4; i++) {
            #pragma unroll
            for (int j = 0; j < 4; j++) acc2[i][j] = 0ull;
        }

        #pragma unroll
        for (int d4 = 0; d4 < 16; d4++) {
            ulonglong2 qv[4], kv[4];
            #pragma unroll
            for (int i = 0; i < 4; i++)
                qv[i] = *(const ulonglong2*)&Qs4[(i0 + i) * 16 + d4];
            #pragma unroll
            for (int j = 0; j < 4; j++)
                kv[j] = *(const ulonglong2*)&Xs4[(j0 + j) * 16 + (d4 ^ tx)];
            #pragma unroll
            for (int i = 0; i < 4; i++) {
                #pragma unroll
                for (int j = 0; j < 4; j++) {
                    fma2(acc2[i][j], qv[i].x, kv[j].x);
                    fma2(acc2[i][j], qv[i].y, kv[j].y);
                }
            }
        }

        float sc[4][4];
        #pragma unroll
        for (int i = 0; i < 4; i++) {
            #pragma unroll
            for (int j = 0; j < 4; j++) {
                float2 v = unpack2(acc2[i][j]);
                sc[i][j] = (v.x + v.y) * 8.0f;
            }
        }
        const int kbase = kt * 64;
        #pragma unroll
        for (int j = 0; j < 4; j++) {
            if (mrow[kbase + j0 + j] != 0) {
                sc[0][j] = -10000.0f; sc[1][j] = -10000.0f;
                sc[2][j] = -10000.0f; sc[3][j] = -10000.0f;
            }
        }

        float p[4][4];
        #pragma unroll
        for (int i = 0; i < 4; i++) {
            float tm = fmaxf(fmaxf(sc[i][0], sc[i][1]), fmaxf(sc[i][2], sc[i][3]));
            #pragma unroll
            for (int w = 1; w < 16; w <<= 1)
                tm = fmaxf(tm, __shfl_xor_sync(0xffffffffu, tm, w));
            float mnew = fmaxf(mrun[i], tm);
            float ts = 0.0f;
            #pragma unroll
            for (int j = 0; j < 4; j++) {
                p[i][j] = expf(sc[i][j] - mnew);
                ts += p[i][j];
            }
            #pragma unroll
            for (int w = 1; w < 16; w <<= 1)
                ts += __shfl_xor_sync(0xffffffffu, ts, w);
            float alpha = expf(mrun[i] - mnew);
            lrun[i] = lrun[i] * alpha + ts;
            mrun[i] = mnew;
            u64 aa = pack2(alpha, alpha);
            mul2(o2[i][0], aa);
            mul2(o2[i][1], aa);
        }
        __syncthreads();

        #pragma unroll
        for (int i = 0; i < 4; i++) {
            float4 pv = make_float4(p[i][0], p[i][1], p[i][2], p[i][3]);
            Xs4[(i0 + i) * 16 + (tx ^ ((i0 + i) >> 2))] = pv;
        }
        __syncthreads();

        #pragma unroll
        for (int j4 = 0; j4 < 16; j4++) {
            float4 pr[4];
            ulonglong2 vv[4];
            #pragma unroll
            for (int i = 0; i < 4; i++)
                pr[i] = Xs4[(i0 + i) * 16 + (j4 ^ ((i0 + i) >> 2))];
            #pragma unroll
            for (int jj = 0; jj < 4; jj++)
                vv[jj] = *(const ulonglong2*)&Vs4[(j4 * 4 + jj) * 16 + tx];
            #pragma unroll
            for (int i = 0; i < 4; i++) {
                const float* pp = (const float*)&pr[i];
                #pragma unroll
                for (int jj = 0; jj < 4; jj++) {
                    u64 ppp = pack2(pp[jj], pp[jj]);
                    fma2(o2[i][0], ppp, vv[jj].x);
                    fma2(o2[i][1], ppp, vv[jj].y);
                }
            }
        }
    }

    #pragma unroll
    for (int i = 0; i < 4; i++) {
        float inv = 1.0f / lrun[i];
        float2 a = unpack2(o2[i][0]);
        float2 b = unpack2(o2[i][1]);
        float4 res = make_float4(a.x * inv, a.y * inv, b.x * inv, b.y * inv);
        int q = qt * 64 + i0 + i;
        float* dst = out + ((size_t)(bb * SEQ + q)) * HID + hh * 64 + tx * 4;
        *(float4*)dst = res;
    }
}

extern "C" void kernel_launch(void* const* d_in, const int* in_sizes, int n_in,
                              void* d_out, int out_size)
{
    const float* hidden = (const float*)d_in[0];
    const int*   mask   = (const int*)  d_in[1];
    const float* w_qkv  = (const float*)d_in[2];
    const float* b_qkv  = (const float*)d_in[3];
    float* out = (float*)d_out;

    cudaFuncSetAttribute(qkv_mma, cudaFuncAttributeMaxDynamicSharedMemorySize, SMEM_TOTAL);

    split_hidden<<<MROWS * KDIM / 4 / 256, 256>>>(hidden);
    split_w<<<dim3(N3 / 64, KDIM / 64), 256>>>(w_qkv);
    qkv_mma<<<dim3(N3 / 128, MROWS / 128), 256, SMEM_TOTAL>>>(b_qkv);
    attn_kernel<<<BATCH * NHEAD * (SEQ / 64), 256>>>(mask, out);
}

// round 8
// speedup vs baseline: 2.6697x; 1.7232x over previous
#include <cuda_runtime.h>
#include <cuda_bf16.h>
#include <cstdint>
#include <math.h>

#define BATCH 8
#define SEQ   1024
#define HID   1024
#define NHEAD 16
#define HDIM  64
#define N3    3072
#define MROWS 8192
#define KDIM  1024

typedef unsigned long long u64;
typedef unsigned int u32;

// ---------------------------------------------------------------------------
// Scratch globals: bf16 2-way splits everywhere
// ---------------------------------------------------------------------------
__device__ __align__(16) __nv_bfloat16 g_Ah[MROWS*KDIM];
__device__ __align__(16) __nv_bfloat16 g_Am[MROWS*KDIM];
__device__ __align__(16) __nv_bfloat16 g_Wh[N3*KDIM];
__device__ __align__(16) __nv_bfloat16 g_Wm[N3*KDIM];

// Q,K,V splits [B,NH,S,HD]
__device__ __align__(16) __nv_bfloat16 g_Qh[BATCH*NHEAD*SEQ*HDIM];
__device__ __align__(16) __nv_bfloat16 g_Qm[BATCH*NHEAD*SEQ*HDIM];
__device__ __align__(16) __nv_bfloat16 g_Kh[BATCH*NHEAD*SEQ*HDIM];
__device__ __align__(16) __nv_bfloat16 g_Km[BATCH*NHEAD*SEQ*HDIM];
__device__ __align__(16) __nv_bfloat16 g_Vh[BATCH*NHEAD*SEQ*HDIM];
__device__ __align__(16) __nv_bfloat16 g_Vm[BATCH*NHEAD*SEQ*HDIM];

// ---------------------------------------------------------------------------
// helpers
// ---------------------------------------------------------------------------
__device__ __forceinline__ u32 su32(const void* p) {
    u32 a;
    asm("{ .reg .u64 t; cvta.to.shared.u64 t, %1; cvt.u32.u64 %0, t; }" : "=r"(a) : "l"(p));
    return a;
}
__device__ __forceinline__ void cp16(u32 sm, const void* g) {
    asm volatile("cp.async.cg.shared.global [%0], [%1], 16;" :: "r"(sm), "l"(g));
}
__device__ __forceinline__ void cp_commit() {
    asm volatile("cp.async.commit_group;" ::: "memory");
}
__device__ __forceinline__ void cp_wait1() {
    asm volatile("cp.async.wait_group 1;" ::: "memory");
}
__device__ __forceinline__ void cp_wait0() {
    asm volatile("cp.async.wait_group 0;" ::: "memory");
}
__device__ __forceinline__ void ldsm4(u32* r, u32 addr) {
    asm volatile("ldmatrix.sync.aligned.m8n8.x4.shared.b16 {%0,%1,%2,%3}, [%4];"
                 : "=r"(r[0]), "=r"(r[1]), "=r"(r[2]), "=r"(r[3]) : "r"(addr));
}
__device__ __forceinline__ void ldsm4t(u32* r, u32 addr) {
    asm volatile("ldmatrix.sync.aligned.m8n8.x4.trans.shared.b16 {%0,%1,%2,%3}, [%4];"
                 : "=r"(r[0]), "=r"(r[1]), "=r"(r[2]), "=r"(r[3]) : "r"(addr));
}
__device__ __forceinline__ void mma16816(float* d, const u32* a, u32 b0, u32 b1) {
    asm volatile(
        "mma.sync.aligned.m16n8k16.row.col.f32.bf16.bf16.f32 "
        "{%0,%1,%2,%3}, {%4,%5,%6,%7}, {%8,%9}, {%0,%1,%2,%3};"
        : "+f"(d[0]), "+f"(d[1]), "+f"(d[2]), "+f"(d[3])
        : "r"(a[0]), "r"(a[1]), "r"(a[2]), "r"(a[3]), "r"(b0), "r"(b1));
}
__device__ __forceinline__ u32 cvtbf2(float lo, float hi) {
    u32 r; asm("cvt.rn.bf16x2.f32 %0, %1, %2;" : "=r"(r) : "f"(hi), "f"(lo)); return r;
}
__device__ __forceinline__ u32 resbf2(float lo, float hi, u32 h) {
    __nv_bfloat162 hb = *reinterpret_cast<__nv_bfloat162*>(&h);
    float2 hf = __bfloat1622float2(hb);
    return cvtbf2(lo - hf.x, hi - hf.y);
}

// ---------------------------------------------------------------------------
// split kernels: fp32 -> bf16 hi/mid
// ---------------------------------------------------------------------------
struct __align__(8) BF4 { __nv_bfloat16 a, b, c, d; };

__device__ __forceinline__ void split2(float x, __nv_bfloat16& h, __nv_bfloat16& m) {
    h = __float2bfloat16(x);
    m = __float2bfloat16(x - __bfloat162float(h));
}

__global__ void __launch_bounds__(256) split_hidden(const float* __restrict__ x) {
    size_t i = (size_t)blockIdx.x * 256 + threadIdx.x;
    float4 v = ((const float4*)x)[i];
    BF4 H, M;
    split2(v.x, H.a, M.a);
    split2(v.y, H.b, M.b);
    split2(v.z, H.c, M.c);
    split2(v.w, H.d, M.d);
    ((BF4*)g_Ah)[i] = H;
    ((BF4*)g_Am)[i] = M;
}

__global__ void __launch_bounds__(256) split_w(const float* __restrict__ w) {
    __shared__ float tile[64][65];
    const int n0 = blockIdx.x * 64, k0 = blockIdx.y * 64;
    const int tid = threadIdx.x;
    #pragma unroll
    for (int i = 0; i < 4; i++) {
        int idx = tid + i * 256;
        int r = idx >> 4, c4 = idx & 15;
        float4 v = *(const float4*)&w[(size_t)(k0 + r) * N3 + n0 + c4 * 4];
        tile[r][c4*4+0] = v.x; tile[r][c4*4+1] = v.y;
        tile[r][c4*4+2] = v.z; tile[r][c4*4+3] = v.w;
    }
    __syncthreads();
    #pragma unroll
    for (int i = 0; i < 4; i++) {
        int idx = tid + i * 256;
        int nl = idx >> 4, k4 = idx & 15;
        BF4 H, M;
        split2(tile[k4*4+0][nl], H.a, M.a);
        split2(tile[k4*4+1][nl], H.b, M.b);
        split2(tile[k4*4+2][nl], H.c, M.c);
        split2(tile[k4*4+3][nl], H.d, M.d);
        size_t o = ((size_t)(n0 + nl) * KDIM + k0 + k4 * 4) >> 2;
        ((BF4*)g_Wh)[o] = H;
        ((BF4*)g_Wm)[o] = M;
    }
}

// ---------------------------------------------------------------------------
// QKV GEMM via mma.sync bf16 (2-split, 3 products). Epilogue emits bf16
// hi/mid splits of Q,K,V.
// ---------------------------------------------------------------------------
#define SMEM_BUF   65536
#define SMEM_TOTAL (2*SMEM_BUF)
#define NCHUNK     16

__device__ __forceinline__ void load_chunk(u32 base, int tid, int k0, int am0, int bn0) {
    #pragma unroll
    for (int j = 0; j < 4; j++) {
        int unit = tid + j * 256;
        int row = unit >> 3, u = unit & 7;
        u32 soff = row * 128 + ((u ^ (row & 7)) << 4);
        size_t ga = (size_t)(am0 + row) * KDIM + k0 + u * 8;
        cp16(base + soff,         g_Ah + ga);
        cp16(base + 16384 + soff, g_Am + ga);
        size_t gb = (size_t)(bn0 + row) * KDIM + k0 + u * 8;
        cp16(base + 32768 + soff, g_Wh + gb);
        cp16(base + 49152 + soff, g_Wm + gb);
    }
}

__global__ void __launch_bounds__(256, 1) qkv_mma(const float* __restrict__ bias) {
    extern __shared__ char smem[];
    const u32 sb = su32(smem);
    const int tid = threadIdx.x;
    const int wid = tid >> 5, lane = tid & 31;
    const int bn = blockIdx.x, bm = blockIdx.y;
    const int am0 = bm * 128, bn0 = bn * 128;
    const int wm = wid >> 2;
    const int wn = wid & 3;

    float acc[4][4][4];
    #pragma unroll
    for (int i = 0; i < 4; i++)
        #pragma unroll
        for (int j = 0; j < 4; j++)
            #pragma unroll
            for (int c = 0; c < 4; c++) acc[i][j][c] = 0.0f;

    const int lrow = (lane & 7) + 8 * ((lane >> 3) & 1);
    const int lu   = lane >> 4;

    load_chunk(sb, tid, 0, am0, bn0);
    cp_commit();

    for (int t = 0; t < NCHUNK; t++) {
        if (t + 1 < NCHUNK) {
            load_chunk(sb + ((t + 1) & 1) * SMEM_BUF, tid, (t + 1) * 64, am0, bn0);
            cp_commit();
            cp_wait1();
        } else {
            cp_wait0();
        }
        __syncthreads();

        const u32 Ah = sb + (t & 1) * SMEM_BUF;
        const u32 Am = Ah + 16384;
        const u32 Bh = Ah + 32768;
        const u32 Bm = Ah + 49152;

        #pragma unroll
        for (int kk = 0; kk < 4; kk++) {
            const int uu = 2 * kk + lu;
            u32 ah[4][4], am[4][4], bh[2][4], bmf[2][4];
            #pragma unroll
            for (int mt = 0; mt < 4; mt++) {
                int row = wm * 64 + mt * 16 + lrow;
                u32 off = row * 128 + ((uu ^ (row & 7)) << 4);
                ldsm4(ah[mt], Ah + off);
                ldsm4(am[mt], Am + off);
            }
            #pragma unroll
            for (int ng = 0; ng < 2; ng++) {
                int row = wn * 32 + ng * 16 + lrow;
                u32 off = row * 128 + ((uu ^ (row & 7)) << 4);
                ldsm4(bh[ng], Bh + off);
                ldsm4(bmf[ng], Bm + off);
            }
            #pragma unroll
            for (int mt = 0; mt < 4; mt++) {
                #pragma unroll
                for (int nt = 0; nt < 4; nt++) {
                    const int ng = nt >> 1, sel = nt & 1;
                    mma16816(acc[mt][nt], ah[mt], bh[ng][sel],  bh[ng][sel + 2]);
                    mma16816(acc[mt][nt], ah[mt], bmf[ng][sel], bmf[ng][sel + 2]);
                    mma16816(acc[mt][nt], am[mt], bh[ng][sel],  bh[ng][sel + 2]);
                }
            }
        }
        __syncthreads();
    }

    // --- epilogue: bias + split to bf16 hi/mid + scatter ---
    const int bb = bm >> 3, ss0 = (bm & 7) * 128;
    const int qr = lane >> 2, qc = (lane & 3) * 2;
    #pragma unroll
    for (int nt = 0; nt < 4; nt++) {
        const int coloc = wn * 32 + nt * 8 + qc;
        const int hf = coloc >> 6;
        const int cb = bn * 2 + hf;
        const int head = cb / 3;
        const int tt = cb - head * 3;
        __nv_bfloat16* dh = (tt == 0) ? g_Qh : (tt == 1) ? g_Kh : g_Vh;
        __nv_bfloat16* dm = (tt == 0) ? g_Qm : (tt == 1) ? g_Km : g_Vm;
        const int c64 = coloc & 63;
        const float2 bv = *(const float2*)&bias[bn * 128 + coloc];
        #pragma unroll
        for (int mt = 0; mt < 4; mt++) {
            #pragma unroll
            for (int half = 0; half < 2; half++) {
                const int mloc = wm * 64 + mt * 16 + qr + half * 8;
                float vx = acc[mt][nt][half * 2 + 0] + bv.x;
                float vy = acc[mt][nt][half * 2 + 1] + bv.y;
                __nv_bfloat162 H, M;
                split2(vx, H.x, M.x);
                split2(vy, H.y, M.y);
                size_t e = ((size_t)(bb * NHEAD + head) * 1024 + ss0 + mloc) * 64 + c64;
                *(__nv_bfloat162*)&dh[e] = H;
                *(__nv_bfloat162*)&dm[e] = M;
            }
        }
    }
}

// ---------------------------------------------------------------------------
// Fused attention via mma.sync bf16: flash-style online softmax.
// CTA = 128 q-rows of one (b,h); 8 warps x m16; 16 key-tiles of 64.
// QK: 3 products (qh kh, qh km, qm kh); PV: 3 products (ph vh, ph vm, pm vh).
// P split to bf16 in registers (acc layout == A-frag layout).
// ---------------------------------------------------------------------------
#define AT_MASK  0
#define AT_QH    4096
#define AT_QM    20480
#define AT_KV    36864
#define AT_STAGE 32768
#define AT_SMEM  (36864 + 2*32768)   // 102400

__device__ __forceinline__ void at_load_kv(u32 sb, int stg, int tid, size_t base, int kt) {
    u32 st = sb + AT_KV + stg * AT_STAGE;
    size_t goff0 = base + (size_t)kt * 64 * 64;
    #pragma unroll
    for (int r = 0; r < 2; r++) {
        int unit = tid + r * 256;
        int row = unit >> 3, u = unit & 7;
        u32 soff = row * 128 + ((u ^ (row & 7)) << 4);
        size_t g = goff0 + row * 64 + u * 8;
        cp16(st + soff,         g_Kh + g);
        cp16(st + 8192 + soff,  g_Km + g);
        cp16(st + 16384 + soff, g_Vh + g);
        cp16(st + 24576 + soff, g_Vm + g);
    }
}

__global__ void __launch_bounds__(256, 1) attn_mma(
    const int* __restrict__ mask, float* __restrict__ out)
{
    extern __shared__ char smem[];
    const u32 sb = su32(smem);
    const int tid = threadIdx.x;
    const int wid = tid >> 5, lane = tid & 31;
    const int qt = blockIdx.x & 7;
    const int bh = blockIdx.x >> 3;
    const int bb = bh >> 4;
    const int hh = bh & 15;
    const size_t base = (size_t)bh * (SEQ * HDIM);

    const int lrow = (lane & 7) + 8 * ((lane >> 3) & 1);
    const int lu   = lane >> 4;
    const int qr   = lane >> 2;
    const int qc2  = (lane & 3) * 2;

    // prologue loads: mask + Q tiles + KV stage 0 | KV stage 1
    cp16(sb + AT_MASK + tid * 16, mask + bb * SEQ + tid * 4);
    {
        size_t q0 = base + (size_t)qt * 128 * 64;
        #pragma unroll
        for (int r = 0; r < 4; r++) {
            int unit = tid + r * 256;
            int row = unit >> 3, u = unit & 7;
            u32 soff = row * 128 + ((u ^ (row & 7)) << 4);
            size_t g = q0 + row * 64 + u * 8;
            cp16(sb + AT_QH + soff, g_Qh + g);
            cp16(sb + AT_QM + soff, g_Qm + g);
        }
    }
    at_load_kv(sb, 0, tid, base, 0);
    cp_commit();
    at_load_kv(sb, 1, tid, base, 1);
    cp_commit();
    cp_wait1();
    __syncthreads();

    // preload Q A-frags
    u32 qha[4][4], qma[4][4];
    #pragma unroll
    for (int kk = 0; kk < 4; kk++) {
        int row = wid * 16 + lrow;
        int u = 2 * kk + lu;
        u32 off = row * 128 + ((u ^ (row & 7)) << 4);
        ldsm4(qha[kk], sb + AT_QH + off);
        ldsm4(qma[kk], sb + AT_QM + off);
    }

    float mrun[2] = { -1e30f, -1e30f };
    float lrun[2] = { 0.0f, 0.0f };
    float oacc[8][4];
    #pragma unroll
    for (int n = 0; n < 8; n++)
        #pragma unroll
        for (int c = 0; c < 4; c++) oacc[n][c] = 0.0f;

    for (int kt = 0; kt < 16; kt++) {
        const u32 st = sb + AT_KV + (kt & 1) * AT_STAGE;

        // --- S = Q K^T ---
        float p[8][4];
        #pragma unroll
        for (int s = 0; s < 8; s++)
            #pragma unroll
            for (int c = 0; c < 4; c++) p[s][c] = 0.0f;

        #pragma unroll
        for (int kk = 0; kk < 4; kk++) {
            const int uu = 2 * kk + lu;
            u32 kh[4][4], km[4][4];
            #pragma unroll
            for (int kg = 0; kg < 4; kg++) {
                int row = kg * 16 + lrow;
                u32 off = row * 128 + ((uu ^ (row & 7)) << 4);
                ldsm4(kh[kg], st + off);
                ldsm4(km[kg], st + 8192 + off);
            }
            #pragma unroll
            for (int s = 0; s < 8; s++) {
                const int kg = s >> 1, hf = s & 1;
                mma16816(p[s], qha[kk], kh[kg][hf], kh[kg][hf + 2]);
                mma16816(p[s], qha[kk], km[kg][hf], km[kg][hf + 2]);
                mma16816(p[s], qma[kk], kh[kg][hf], kh[kg][hf + 2]);
            }
        }

        // --- mask + scale (matches reference: scale first, masked -> -10000) ---
        #pragma unroll
        for (int s = 0; s < 8; s++) {
            int2 mv = *(const int2*)(smem + AT_MASK + (size_t)(kt * 64 + s * 8 + qc2) * 4);
            p[s][0] = mv.x ? -10000.0f : p[s][0] * 8.0f;
            p[s][1] = mv.y ? -10000.0f : p[s][1] * 8.0f;
            p[s][2] = mv.x ? -10000.0f : p[s][2] * 8.0f;
            p[s][3] = mv.y ? -10000.0f : p[s][3] * 8.0f;
        }

        // --- online softmax (per row-half; quad reduce over lane%4) ---
        #pragma unroll
        for (int h = 0; h < 2; h++) {
            float tm = -1e30f;
            #pragma unroll
            for (int s = 0; s < 8; s++)
                tm = fmaxf(tm, fmaxf(p[s][2*h], p[s][2*h + 1]));
            tm = fmaxf(tm, __shfl_xor_sync(0xffffffffu, tm, 1));
            tm = fmaxf(tm, __shfl_xor_sync(0xffffffffu, tm, 2));
            float mnew = fmaxf(mrun[h], tm);
            float ts = 0.0f;
            #pragma unroll
            for (int s = 0; s < 8; s++) {
                p[s][2*h]     = __expf(p[s][2*h]     - mnew);
                p[s][2*h + 1] = __expf(p[s][2*h + 1] - mnew);
                ts += p[s][2*h] + p[s][2*h + 1];
            }
            ts += __shfl_xor_sync(0xffffffffu, ts, 1);
            ts += __shfl_xor_sync(0xffffffffu, ts, 2);
            float alpha = __expf(mrun[h] - mnew);
            lrun[h] = lrun[h] * alpha + ts;
            mrun[h] = mnew;
            #pragma unroll
            for (int n = 0; n < 8; n++) {
                oacc[n][2*h]     *= alpha;
                oacc[n][2*h + 1] *= alpha;
            }
        }

        // --- O += P V ---
        #pragma unroll
        for (int kg = 0; kg < 4; kg++) {
            u32 pha[4], pma[4];
            pha[0] = cvtbf2(p[2*kg][0],     p[2*kg][1]);
            pha[1] = cvtbf2(p[2*kg][2],     p[2*kg][3]);
            pha[2] = cvtbf2(p[2*kg + 1][0], p[2*kg + 1][1]);
            pha[3] = cvtbf2(p[2*kg + 1][2], p[2*kg + 1][3]);
            pma[0] = resbf2(p[2*kg][0],     p[2*kg][1],     pha[0]);
            pma[1] = resbf2(p[2*kg][2],     p[2*kg][3],     pha[1]);
            pma[2] = resbf2(p[2*kg + 1][0], p[2*kg + 1][1], pha[2]);
            pma[3] = resbf2(p[2*kg + 1][2], p[2*kg + 1][3], pha[3]);

            u32 vh[4][4], vm[4][4];
            #pragma unroll
            for (int ng = 0; ng < 4; ng++) {
                int row = kg * 16 + lrow;
                int u = 2 * ng + lu;
                u32 off = row * 128 + ((u ^ (row & 7)) << 4);
                ldsm4t(vh[ng], st + 16384 + off);
                ldsm4t(vm[ng], st + 24576 + off);
            }
            #pragma unroll
            for (int n8 = 0; n8 < 8; n8++) {
                const int ng = n8 >> 1, hf = n8 & 1;
                mma16816(oacc[n8], pha, vh[ng][2*hf], vh[ng][2*hf + 1]);
                mma16816(oacc[n8], pha, vm[ng][2*hf], vm[ng][2*hf + 1]);
                mma16816(oacc[n8], pma, vh[ng][2*hf], vh[ng][2*hf + 1]);
            }
        }

        __syncthreads();
        if (kt + 2 < 16) {
            at_load_kv(sb, kt & 1, tid, base, kt + 2);
            cp_commit();
        }
        if (kt + 1 < 16) {
            if (kt + 2 < 16) cp_wait1(); else cp_wait0();
            __syncthreads();
        }
    }

    // --- epilogue ---
    #pragma unroll
    for (int h = 0; h < 2; h++) {
        float inv = 1.0f / lrun[h];
        int qrow = qt * 128 + wid * 16 + qr + h * 8;
        float* drow = out + ((size_t)(bb * SEQ + qrow)) * HID + hh * 64;
        #pragma unroll
        for (int n8 = 0; n8 < 8; n8++) {
            float2 v;
            v.x = oacc[n8][2*h]     * inv;
            v.y = oacc[n8][2*h + 1] * inv;
            *(float2*)&drow[n8 * 8 + qc2] = v;
        }
    }
}

extern "C" void kernel_launch(void* const* d_in, const int* in_sizes, int n_in,
                              void* d_out, int out_size)
{
    const float* hidden = (const float*)d_in[0];
    const int*   mask   = (const int*)  d_in[1];
    const float* w_qkv  = (const float*)d_in[2];
    const float* b_qkv  = (const float*)d_in[3];
    float* out = (float*)d_out;

    cudaFuncSetAttribute(qkv_mma, cudaFuncAttributeMaxDynamicSharedMemorySize, SMEM_TOTAL);
    cudaFuncSetAttribute(attn_mma, cudaFuncAttributeMaxDynamicSharedMemorySize, AT_SMEM);

    split_hidden<<<MROWS * KDIM / 4 / 256, 256>>>(hidden);
    split_w<<<dim3(N3 / 64, KDIM / 64), 256>>>(w_qkv);
    qkv_mma<<<dim3(N3 / 128, MROWS / 128), 256, SMEM_TOTAL>>>(b_qkv);
    attn_mma<<<BATCH * NHEAD * (SEQ / 128), 256, AT_SMEM>>>(mask, out);
}

// round 13
// speedup vs baseline: 2.6832x; 1.0051x over previous
#include <cuda_runtime.h>
#include <cuda_bf16.h>
#include <cstdint>
#include <math.h>

#define BATCH 8
#define SEQ   1024
#define HID   1024
#define NHEAD 16
#define HDIM  64
#define N3    3072
#define MROWS 8192
#define KDIM  1024

typedef unsigned long long u64;
typedef unsigned int u32;

// ---------------------------------------------------------------------------
// Scratch globals: bf16 2-way splits everywhere
// ---------------------------------------------------------------------------
__device__ __align__(16) __nv_bfloat16 g_Ah[MROWS*KDIM];
__device__ __align__(16) __nv_bfloat16 g_Am[MROWS*KDIM];
__device__ __align__(16) __nv_bfloat16 g_Wh[N3*KDIM];
__device__ __align__(16) __nv_bfloat16 g_Wm[N3*KDIM];

__device__ __align__(16) __nv_bfloat16 g_Qh[BATCH*NHEAD*SEQ*HDIM];
__device__ __align__(16) __nv_bfloat16 g_Qm[BATCH*NHEAD*SEQ*HDIM];
__device__ __align__(16) __nv_bfloat16 g_Kh[BATCH*NHEAD*SEQ*HDIM];
__device__ __align__(16) __nv_bfloat16 g_Km[BATCH*NHEAD*SEQ*HDIM];
__device__ __align__(16) __nv_bfloat16 g_Vh[BATCH*NHEAD*SEQ*HDIM];
__device__ __align__(16) __nv_bfloat16 g_Vm[BATCH*NHEAD*SEQ*HDIM];

// ---------------------------------------------------------------------------
// helpers
// ---------------------------------------------------------------------------
__device__ __forceinline__ u32 su32(const void* p) {
    u32 a;
    asm("{ .reg .u64 t; cvta.to.shared.u64 t, %1; cvt.u32.u64 %0, t; }" : "=r"(a) : "l"(p));
    return a;
}
__device__ __forceinline__ void cp16(u32 sm, const void* g) {
    asm volatile("cp.async.cg.shared.global [%0], [%1], 16;" :: "r"(sm), "l"(g));
}
__device__ __forceinline__ void cp_commit() {
    asm volatile("cp.async.commit_group;" ::: "memory");
}
__device__ __forceinline__ void cp_wait1() {
    asm volatile("cp.async.wait_group 1;" ::: "memory");
}
__device__ __forceinline__ void cp_wait0() {
    asm volatile("cp.async.wait_group 0;" ::: "memory");
}
__device__ __forceinline__ void ldsm4(u32* r, u32 addr) {
    asm volatile("ldmatrix.sync.aligned.m8n8.x4.shared.b16 {%0,%1,%2,%3}, [%4];"
                 : "=r"(r[0]), "=r"(r[1]), "=r"(r[2]), "=r"(r[3]) : "r"(addr));
}
__device__ __forceinline__ void ldsm4t(u32* r, u32 addr) {
    asm volatile("ldmatrix.sync.aligned.m8n8.x4.trans.shared.b16 {%0,%1,%2,%3}, [%4];"
                 : "=r"(r[0]), "=r"(r[1]), "=r"(r[2]), "=r"(r[3]) : "r"(addr));
}
__device__ __forceinline__ void mma16816(float* d, const u32* a, u32 b0, u32 b1) {
    asm volatile(
        "mma.sync.aligned.m16n8k16.row.col.f32.bf16.bf16.f32 "
        "{%0,%1,%2,%3}, {%4,%5,%6,%7}, {%8,%9}, {%0,%1,%2,%3};"
        : "+f"(d[0]), "+f"(d[1]), "+f"(d[2]), "+f"(d[3])
        : "r"(a[0]), "r"(a[1]), "r"(a[2]), "r"(a[3]), "r"(b0), "r"(b1));
}
__device__ __forceinline__ u32 cvtbf2(float lo, float hi) {
    u32 r; asm("cvt.rn.bf16x2.f32 %0, %1, %2;" : "=r"(r) : "f"(hi), "f"(lo)); return r;
}
__device__ __forceinline__ u32 resbf2(float lo, float hi, u32 h) {
    __nv_bfloat162 hb = *reinterpret_cast<__nv_bfloat162*>(&h);
    float2 hf = __bfloat1622float2(hb);
    return cvtbf2(lo - hf.x, hi - hf.y);
}

// ---------------------------------------------------------------------------
// split kernels: fp32 -> bf16 hi/mid
// ---------------------------------------------------------------------------
struct __align__(8) BF4 { __nv_bfloat16 a, b, c, d; };

__device__ __forceinline__ void split2(float x, __nv_bfloat16& h, __nv_bfloat16& m) {
    h = __float2bfloat16(x);
    m = __float2bfloat16(x - __bfloat162float(h));
}

__global__ void __launch_bounds__(256) split_hidden(const float* __restrict__ x) {
    size_t i = (size_t)blockIdx.x * 256 + threadIdx.x;
    float4 v = ((const float4*)x)[i];
    BF4 H, M;
    split2(v.x, H.a, M.a);
    split2(v.y, H.b, M.b);
    split2(v.z, H.c, M.c);
    split2(v.w, H.d, M.d);
    ((BF4*)g_Ah)[i] = H;
    ((BF4*)g_Am)[i] = M;
}

__global__ void __launch_bounds__(256) split_w(const float* __restrict__ w) {
    __shared__ float tile[64][65];
    const int n0 = blockIdx.x * 64, k0 = blockIdx.y * 64;
    const int tid = threadIdx.x;
    #pragma unroll
    for (int i = 0; i < 4; i++) {
        int idx = tid + i * 256;
        int r = idx >> 4, c4 = idx & 15;
        float4 v = *(const float4*)&w[(size_t)(k0 + r) * N3 + n0 + c4 * 4];
        tile[r][c4*4+0] = v.x; tile[r][c4*4+1] = v.y;
        tile[r][c4*4+2] = v.z; tile[r][c4*4+3] = v.w;
    }
    __syncthreads();
    #pragma unroll
    for (int i = 0; i < 4; i++) {
        int idx = tid + i * 256;
        int nl = idx >> 4, k4 = idx & 15;
        BF4 H, M;
        split2(tile[k4*4+0][nl], H.a, M.a);
        split2(tile[k4*4+1][nl], H.b, M.b);
        split2(tile[k4*4+2][nl], H.c, M.c);
        split2(tile[k4*4+3][nl], H.d, M.d);
        size_t o = ((size_t)(n0 + nl) * KDIM + k0 + k4 * 4) >> 2;
        ((BF4*)g_Wh)[o] = H;
        ((BF4*)g_Wm)[o] = M;
    }
}

// ---------------------------------------------------------------------------
// QKV GEMM via mma.sync bf16 (2-split, 3 products).
// K-chunk 32; each 128B smem row holds [hi 64B | mid 64B] for one tile row,
// XOR-swizzled u^(row&7). 2-stage cp.async, 2 CTAs/SM.
// ---------------------------------------------------------------------------
#define SMEM_BUF   32768
#define SMEM_TOTAL (2*SMEM_BUF)
#define NCHUNK     32

__device__ __forceinline__ void load_chunk(u32 base, int tid, int k0, int am0, int bn0) {
    #pragma unroll
    for (int j = 0; j < 4; j++) {
        int unit = tid + j * 256;            // 0..1023
        int row = unit >> 3, u = unit & 7;
        u32 soff = row * 128 + ((u ^ (row & 7)) << 4);
        size_t goff = (size_t)k0 + ((u & 3) * 8);
        const __nv_bfloat16* sa = (u < 4) ? g_Ah : g_Am;
        const __nv_bfloat16* sb = (u < 4) ? g_Wh : g_Wm;
        cp16(base + soff,         sa + (size_t)(am0 + row) * KDIM + goff);
        cp16(base + 16384 + soff, sb + (size_t)(bn0 + row) * KDIM + goff);
    }
}

__global__ void __launch_bounds__(256, 2) qkv_mma(const float* __restrict__ bias) {
    extern __shared__ char smem[];
    const u32 sb = su32(smem);
    const int tid = threadIdx.x;
    const int wid = tid >> 5, lane = tid & 31;
    const int bn = blockIdx.x, bm = blockIdx.y;
    const int am0 = bm * 128, bn0 = bn * 128;
    const int wm = wid >> 2;
    const int wn = wid & 3;

    float acc[4][4][4];
    #pragma unroll
    for (int i = 0; i < 4; i++)
        #pragma unroll
        for (int j = 0; j < 4; j++)
            #pragma unroll
            for (int c = 0; c < 4; c++) acc[i][j][c] = 0.0f;

    const int lrow = (lane & 7) + 8 * ((lane >> 3) & 1);
    const int lu   = lane >> 4;

    load_chunk(sb, tid, 0, am0, bn0);
    cp_commit();

    for (int t = 0; t < NCHUNK; t++) {
        if (t + 1 < NCHUNK) {
            load_chunk(sb + ((t + 1) & 1) * SMEM_BUF, tid, (t + 1) * 32, am0, bn0);
            cp_commit();
            cp_wait1();
        } else {
            cp_wait0();
        }
        __syncthreads();

        const u32 Abuf = sb + (t & 1) * SMEM_BUF;
        const u32 Bbuf = Abuf + 16384;

        #pragma unroll
        for (int kk = 0; kk < 2; kk++) {
            const int uh = 2 * kk + lu;        // hi units 0..3
            const int um = 4 + 2 * kk + lu;    // mid units 4..7
            u32 ah[4][4], am[4][4], bh[2][4], bmf[2][4];
            #pragma unroll
            for (int mt = 0; mt < 4; mt++) {
                int row = wm * 64 + mt * 16 + lrow;
                u32 rbase = row * 128;
                ldsm4(ah[mt], Abuf + rbase + ((uh ^ (row & 7)) << 4));
                ldsm4(am[mt], Abuf + rbase + ((um ^ (row & 7)) << 4));
            }
            #pragma unroll
            for (int ng = 0; ng < 2; ng++) {
                int row = wn * 32 + ng * 16 + lrow;
                u32 rbase = row * 128;
                ldsm4(bh[ng],  Bbuf + rbase + ((uh ^ (row & 7)) << 4));
                ldsm4(bmf[ng], Bbuf + rbase + ((um ^ (row & 7)) << 4));
            }
            #pragma unroll
            for (int mt = 0; mt < 4; mt++) {
                #pragma unroll
                for (int nt = 0; nt < 4; nt++) {
                    const int ng = nt >> 1, sel = nt & 1;
                    mma16816(acc[mt][nt], ah[mt], bh[ng][sel],  bh[ng][sel + 2]);
                    mma16816(acc[mt][nt], ah[mt], bmf[ng][sel], bmf[ng][sel + 2]);
                    mma16816(acc[mt][nt], am[mt], bh[ng][sel],  bh[ng][sel + 2]);
                }
            }
        }
        __syncthreads();
    }

    // --- epilogue: bias + split to bf16 hi/mid + scatter ---
    const int bb = bm >> 3, ss0 = (bm & 7) * 128;
    const int qr = lane >> 2, qc = (lane & 3) * 2;
    #pragma unroll
    for (int nt = 0; nt < 4; nt++) {
        const int coloc = wn * 32 + nt * 8 + qc;
        const int hf = coloc >> 6;
        const int cb = bn * 2 + hf;
        const int head = cb / 3;
        const int tt = cb - head * 3;
        __nv_bfloat16* dh = (tt == 0) ? g_Qh : (tt == 1) ? g_Kh : g_Vh;
        __nv_bfloat16* dm = (tt == 0) ? g_Qm : (tt == 1) ? g_Km : g_Vm;
        const int c64 = coloc & 63;
        const float2 bv = *(const float2*)&bias[bn * 128 + coloc];
        #pragma unroll
        for (int mt = 0; mt < 4; mt++) {
            #pragma unroll
            for (int half = 0; half < 2; half++) {
                const int mloc = wm * 64 + mt * 16 + qr + half * 8;
                float vx = acc[mt][nt][half * 2 + 0] + bv.x;
                float vy = acc[mt][nt][half * 2 + 1] + bv.y;
                __nv_bfloat162 H, M;
                split2(vx, H.x, M.x);
                split2(vy, H.y, M.y);
                size_t e = ((size_t)(bb * NHEAD + head) * 1024 + ss0 + mloc) * 64 + c64;
                *(__nv_bfloat162*)&dh[e] = H;
                *(__nv_bfloat162*)&dm[e] = M;
            }
        }
    }
}

// ---------------------------------------------------------------------------
// Fused attention via mma.sync bf16, flash-style online softmax.
// CTA = 64 q-rows (4 warps x m16), 128 threads; 2 CTAs/SM.
// ---------------------------------------------------------------------------
#define AT_MASK  0
#define AT_QH    4096
#define AT_QM    12288
#define AT_KV    20480
#define AT_STAGE 32768
#define AT_SMEM  (20480 + 2*32768)   // 86016

__device__ __forceinline__ void at_load_kv(u32 sb, int stg, int tid, size_t base, int kt) {
    u32 st = sb + AT_KV + stg * AT_STAGE;
    size_t goff0 = base + (size_t)kt * 64 * 64;
    #pragma unroll
    for (int r = 0; r < 4; r++) {
        int unit = tid + r * 128;
        int row = unit >> 3, u = unit & 7;
        u32 soff = row * 128 + ((u ^ (row & 7)) << 4);
        size_t g = goff0 + row * 64 + u * 8;
        cp16(st + soff,         g_Kh + g);
        cp16(st + 8192 + soff,  g_Km + g);
        cp16(st + 16384 + soff, g_Vh + g);
        cp16(st + 24576 + soff, g_Vm + g);
    }
}

__global__ void __launch_bounds__(128) attn_mma(
    const int* __restrict__ mask, float* __restrict__ out)
{
    extern __shared__ char smem[];
    const u32 sb = su32(smem);
    const int tid = threadIdx.x;
    const int wid = tid >> 5, lane = tid & 31;
    const int qt = blockIdx.x & 15;
    const int bh = blockIdx.x >> 4;
    const int bb = bh >> 4;
    const int hh = bh & 15;
    const size_t base = (size_t)bh * (SEQ * HDIM);

    const int lrow = (lane & 7) + 8 * ((lane >> 3) & 1);
    const int lu   = lane >> 4;
    const int qr   = lane >> 2;
    const int qc2  = (lane & 3) * 2;

    // prologue: mask + Q tile + KV stages 0/1
    #pragma unroll
    for (int r = 0; r < 2; r++)
        cp16(sb + AT_MASK + (tid + r * 128) * 16, mask + bb * SEQ + (tid + r * 128) * 4);
    {
        size_t q0 = base + (size_t)qt * 64 * 64;
        #pragma unroll
        for (int r = 0; r < 4; r++) {
            int unit = tid + r * 128;
            int row = unit >> 3, u = unit & 7;
            u32 soff = row * 128 + ((u ^ (row & 7)) << 4);
            size_t g = q0 + row * 64 + u * 8;
            cp16(sb + AT_QH + soff, g_Qh + g);
            cp16(sb + AT_QM + soff, g_Qm + g);
        }
    }
    at_load_kv(sb, 0, tid, base, 0);
    cp_commit();
    at_load_kv(sb, 1, tid, base, 1);
    cp_commit();
    cp_wait1();
    __syncthreads();

    // preload Q A-frags
    u32 qha[4][4], qma[4][4];
    #pragma unroll
    for (int kk = 0; kk < 4; kk++) {
        int row = wid * 16 + lrow;
        int u = 2 * kk + lu;
        u32 off = row * 128 + ((u ^ (row & 7)) << 4);
        ldsm4(qha[kk], sb + AT_QH + off);
        ldsm4(qma[kk], sb + AT_QM + off);
    }

    float mrun[2] = { -1e30f, -1e30f };
    float lrun[2] = { 0.0f, 0.0f };
    float oacc[8][4];
    #pragma unroll
    for (int n = 0; n < 8; n++)
        #pragma unroll
        for (int c = 0; c < 4; c++) oacc[n][c] = 0.0f;

    for (int kt = 0; kt < 16; kt++) {
        const u32 st = sb + AT_KV + (kt & 1) * AT_STAGE;

        // --- S = Q K^T ---
        float p[8][4];
        #pragma unroll
        for (int s = 0; s < 8; s++)
            #pragma unroll
            for (int c = 0; c < 4; c++) p[s][c] = 0.0f;

        #pragma unroll
        for (int kk = 0; kk < 4; kk++) {
            const int uu = 2 * kk + lu;
            u32 kh[4][4], km[4][4];
            #pragma unroll
            for (int kg = 0; kg < 4; kg++) {
                int row = kg * 16 + lrow;
                u32 off = row * 128 + ((uu ^ (row & 7)) << 4);
                ldsm4(kh[kg], st + off);
                ldsm4(km[kg], st + 8192 + off);
            }
            #pragma unroll
            for (int s = 0; s < 8; s++) {
                const int kg = s >> 1, hf = s & 1;
                mma16816(p[s], qha[kk], kh[kg][hf], kh[kg][hf + 2]);
                mma16816(p[s], qha[kk], km[kg][hf], km[kg][hf + 2]);
                mma16816(p[s], qma[kk], kh[kg][hf], kh[kg][hf + 2]);
            }
        }

        // --- mask + scale ---
        #pragma unroll
        for (int s = 0; s < 8; s++) {
            int2 mv = *(const int2*)(smem + AT_MASK + (size_t)(kt * 64 + s * 8 + qc2) * 4);
            p[s][0] = mv.x ? -10000.0f : p[s][0] * 8.0f;
            p[s][1] = mv.y ? -10000.0f : p[s][1] * 8.0f;
            p[s][2] = mv.x ? -10000.0f : p[s][2] * 8.0f;
            p[s][3] = mv.y ? -10000.0f : p[s][3] * 8.0f;
        }

        // --- online softmax ---
        #pragma unroll
        for (int h = 0; h < 2; h++) {
            float tm = -1e30f;
            #pragma unroll
            for (int s = 0; s < 8; s++)
                tm = fmaxf(tm, fmaxf(p[s][2*h], p[s][2*h + 1]));
            tm = fmaxf(tm, __shfl_xor_sync(0xffffffffu, tm, 1));
            tm = fmaxf(tm, __shfl_xor_sync(0xffffffffu, tm, 2));
            float mnew = fmaxf(mrun[h], tm);
            float ts = 0.0f;
            #pragma unroll
            for (int s = 0; s < 8; s++) {
                p[s][2*h]     = __expf(p[s][2*h]     - mnew);
                p[s][2*h + 1] = __expf(p[s][2*h + 1] - mnew);
                ts += p[s][2*h] + p[s][2*h + 1];
            }
            ts += __shfl_xor_sync(0xffffffffu, ts, 1);
            ts += __shfl_xor_sync(0xffffffffu, ts, 2);
            float alpha = __expf(mrun[h] - mnew);
            lrun[h] = lrun[h] * alpha + ts;
            mrun[h] = mnew;
            #pragma unroll
            for (int n = 0; n < 8; n++) {
                oacc[n][2*h]     *= alpha;
                oacc[n][2*h + 1] *= alpha;
            }
        }

        // --- O += P V ---
        #pragma unroll
        for (int kg = 0; kg < 4; kg++) {
            u32 pha[4], pma[4];
            pha[0] = cvtbf2(p[2*kg][0],     p[2*kg][1]);
            pha[1] = cvtbf2(p[2*kg][2],     p[2*kg][3]);
            pha[2] = cvtbf2(p[2*kg + 1][0], p[2*kg + 1][1]);
            pha[3] = cvtbf2(p[2*kg + 1][2], p[2*kg + 1][3]);
            pma[0] = resbf2(p[2*kg][0],     p[2*kg][1],     pha[0]);
            pma[1] = resbf2(p[2*kg][2],     p[2*kg][3],     pha[1]);
            pma[2] = resbf2(p[2*kg + 1][0], p[2*kg + 1][1], pha[2]);
            pma[3] = resbf2(p[2*kg + 1][2], p[2*kg + 1][3], pha[3]);

            u32 vh[4][4], vm[4][4];
            #pragma unroll
            for (int ng = 0; ng < 4; ng++) {
                int row = kg * 16 + lrow;
                int u = 2 * ng + lu;
                u32 off = row * 128 + ((u ^ (row & 7)) << 4);
                ldsm4t(vh[ng], st + 16384 + off);
                ldsm4t(vm[ng], st + 24576 + off);
            }
            #pragma unroll
            for (int n8 = 0; n8 < 8; n8++) {
                const int ng = n8 >> 1, hf = n8 & 1;
                mma16816(oacc[n8], pha, vh[ng][2*hf], vh[ng][2*hf + 1]);
                mma16816(oacc[n8], pha, vm[ng][2*hf], vm[ng][2*hf + 1]);
                mma16816(oacc[n8], pma, vh[ng][2*hf], vh[ng][2*hf + 1]);
            }
        }

        __syncthreads();
        if (kt + 2 < 16) {
            at_load_kv(sb, kt & 1, tid, base, kt + 2);
            cp_commit();
        }
        if (kt + 1 < 16) {
            if (kt + 2 < 16) cp_wait1(); else cp_wait0();
            __syncthreads();
        }
    }

    // --- epilogue ---
    #pragma unroll
    for (int h = 0; h < 2; h++) {
        float inv = 1.0f / lrun[h];
        int qrow = qt * 64 + wid * 16 + qr + h * 8;
        float* drow = out + ((size_t)(bb * SEQ + qrow)) * HID + hh * 64;
        #pragma unroll
        for (int n8 = 0; n8 < 8; n8++) {
            float2 v;
            v.x = oacc[n8][2*h]     * inv;
            v.y = oacc[n8][2*h + 1] * inv;
            *(float2*)&drow[n8 * 8 + qc2] = v;
        }
    }
}

extern "C" void kernel_launch(void* const* d_in, const int* in_sizes, int n_in,
                              void* d_out, int out_size)
{
    const float* hidden = (const float*)d_in[0];
    const int*   mask   = (const int*)  d_in[1];
    const float* w_qkv  = (const float*)d_in[2];
    const float* b_qkv  = (const float*)d_in[3];
    float* out = (float*)d_out;

    cudaFuncSetAttribute(qkv_mma, cudaFuncAttributeMaxDynamicSharedMemorySize, SMEM_TOTAL);
    cudaFuncSetAttribute(attn_mma, cudaFuncAttributeMaxDynamicSharedMemorySize, AT_SMEM);

    split_hidden<<<MROWS * KDIM / 4 / 256, 256>>>(hidden);
    split_w<<<dim3(N3 / 64, KDIM / 64), 256>>>(w_qkv);
    qkv_mma<<<dim3(N3 / 128, MROWS / 128), 256, SMEM_TOTAL>>>(b_qkv);
    attn_mma<<<BATCH * NHEAD * (SEQ / 64), 128, AT_SMEM>>>(mask, out);
}